// round 7
// baseline (speedup 1.0000x reference)
#include <cuda_runtime.h>
#include <math_constants.h>

// Problem constants
constexpr int NB = 128, NK = 8, NV = 50257, NL = 64, NMAXL = 128, NA = 512, ND = 1024;
constexpr int NEOS = 2;
constexpr int ROWS = NB * NK;   // 1024

// Output layout (single float32 dtype; integer outputs written as floats)
constexpr size_t OFF0 = 0;
constexpr size_t OFF1 = OFF0 + (size_t)NB * NK;
constexpr size_t OFF2 = OFF1 + (size_t)NB * NK * (NL + 1);
constexpr size_t OFF3 = OFF2 + (size_t)NB * NK;
constexpr size_t OFF4 = OFF3 + (size_t)NB * NK;
constexpr size_t OFF5 = OFF4 + (size_t)NB * NK * NMAXL;
constexpr size_t OFF6 = OFF5 + (size_t)NB * NK;
constexpr size_t OFF7 = OFF6 + (size_t)NB * NK * NA;
constexpr size_t OFF8 = OFF7 + (size_t)NB * NK * ND;

// Device scratch
__device__ float g_top_val[ROWS * 8];
__device__ int   g_top_idx[ROWS * 8];
__device__ float g_row_c[ROWS];
__device__ float g_eos[ROWS];

// Packed orderable key: larger == (larger val, then smaller idx). 0 = sentinel.
__device__ __forceinline__ unsigned long long pack_key(float v, unsigned int idx) {
    unsigned int u = __float_as_uint(v);
    u = (u & 0x80000000u) ? ~u : (u | 0x80000000u);
    return ((unsigned long long)u << 32) | (unsigned long long)(0xFFFFFFFFu - idx);
}
__device__ __forceinline__ float key_val(unsigned long long k) {
    unsigned int u = (unsigned int)(k >> 32);
    unsigned int bits = (u & 0x80000000u) ? (u ^ 0x80000000u) : ~u;
    return __uint_as_float(bits);
}
__device__ __forceinline__ unsigned key_low(unsigned long long k) {
    return 0xFFFFFFFFu - (unsigned int)(k & 0xFFFFFFFFu);
}

constexpr int CAP = 1024;

struct RedSmem {
    unsigned long long keys[16];
    unsigned long long win;
};

// Block-wide argmax over packed keys (512 threads). All threads must call.
__device__ __forceinline__ unsigned long long block_argmax(unsigned long long my,
                                                           RedSmem& rs, int tid) {
    int lane = tid & 31, wid = tid >> 5;
    unsigned long long k = my;
#pragma unroll
    for (int off = 16; off; off >>= 1) {
        unsigned long long o = __shfl_xor_sync(0xFFFFFFFFu, k, off);
        if (o > k) k = o;
    }
    if (lane == 0) rs.keys[wid] = k;
    __syncthreads();
    if (tid < 16) {
        unsigned long long kk = rs.keys[tid];
#pragma unroll
        for (int off = 8; off; off >>= 1) {
            unsigned long long o = __shfl_xor_sync(0x0000FFFFu, kk, off);
            if (o > kk) kk = o;
        }
        if (tid == 0) rs.win = kk;
    }
    __syncthreads();
    return rs.win;
}

// Process one float4 chunk: accumulate exp, rare-push candidates >= tau.
#define PROC_CHUNK(q, vv)                                                          \
    do {                                                                           \
        sum0 += __expf((q).x); sum1 += __expf((q).y);                              \
        sum2 += __expf((q).z); sum3 += __expf((q).w);                              \
        float mm = fmaxf(fmaxf((q).x, (q).y), fmaxf((q).z, (q).w));                \
        if (__any_sync(0xFFFFFFFFu, mm >= tau)) {                                  \
            unsigned base = (unsigned)(pre + 4 * (vv));                            \
            if ((q).x >= tau) { int p = atomicAdd(&s_cnt, 1); if (p < CAP) s_buf[p] = pack_key((q).x, base + 0); } \
            if ((q).y >= tau) { int p = atomicAdd(&s_cnt, 1); if (p < CAP) s_buf[p] = pack_key((q).y, base + 1); } \
            if ((q).z >= tau) { int p = atomicAdd(&s_cnt, 1); if (p < CAP) s_buf[p] = pack_key((q).z, base + 2); } \
            if ((q).w >= tau) { int p = atomicAdd(&s_cnt, 1); if (p < CAP) s_buf[p] = pack_key((q).w, base + 3); } \
        }                                                                          \
    } while (0)

// ---------------------------------------------------------------------------
// Kernel 1: per (b,k) row — fused sumexp + threshold-filtered top-8
// ---------------------------------------------------------------------------
__global__ __launch_bounds__(512) void k_rows(const float* __restrict__ logits,
                                              const float* __restrict__ cand_scores) {
    const int row = blockIdx.x;
    const int tid = threadIdx.x;
    const float* rl = logits + (long long)row * NV;

    __shared__ unsigned long long s_buf[CAP];
    __shared__ float s_red[512];
    __shared__ RedSmem s_rs;
    __shared__ int s_cnt;
    __shared__ float s_eosv;
    __shared__ float s_tau;

    if (tid == 0) s_cnt = 0;

    // ---- Phase 1: tau from the first 8192 elements (coalesced) ----
    // Per-thread max over 16 strided samples (EOS excluded), then tau = 8th
    // largest of the 512 maxima => tau <= true 8th-largest non-EOS value.
    {
        float m = -CUDART_INF_F;
#pragma unroll
        for (int i = 0; i < 16; ++i) {
            int idx = i * 512 + tid;
            float x = rl[idx];
            if (idx == NEOS) { s_eosv = x; x = -CUDART_INF_F; }
            m = fmaxf(m, x);
        }
        unsigned long long mk = pack_key(m, (unsigned)tid);
        unsigned long long win = 0;
        for (int r = 0; r < 8; ++r) {
            win = block_argmax(mk, s_rs, tid);
            if (mk == win) mk = 0;
        }
        if (tid == 0) s_tau = key_val(win);
        __syncthreads();
    }
    const float tau = s_tau;

    // ---- Phase 2: full scan: sumexp + push candidates (x >= tau) ----
    float sum0 = 0.f, sum1 = 0.f, sum2 = 0.f, sum3 = 0.f;

    // alignment peel (row base is only 4B aligned)
    const int pre = (int)(((16u - ((unsigned)(unsigned long long)rl & 15u)) & 15u) >> 2);
    const int nvec = (NV - pre) >> 2;
    const int F = nvec >> 9;              // full 512-wide float4 chunks
    const int tstart = pre + nvec * 4;

    if (tid < pre) {
        float x = rl[tid];
        sum0 += __expf(x);
        if (x >= tau) {
            int p = atomicAdd(&s_cnt, 1);
            if (p < CAP) s_buf[p] = pack_key(x, (unsigned)tid);
        }
    }

    const float4* rl4 = (const float4*)(rl + pre);

    // Main loop: 4 loads issued up-front (MLP=4/warp), then process.
    // All 512 threads active in every iteration -> __any_sync always full-warp.
    int it = 0;
    for (; it + 4 <= F; it += 4) {
        int v0 = tid + (it << 9);
        int v1 = v0 + 512, v2 = v0 + 1024, v3 = v0 + 1536;
        float4 a = rl4[v0];
        float4 b = rl4[v1];
        float4 c = rl4[v2];
        float4 d = rl4[v3];
        PROC_CHUNK(a, v0);
        PROC_CHUNK(b, v1);
        PROC_CHUNK(c, v2);
        PROC_CHUNK(d, v3);
    }
    for (; it < F; ++it) {   // leftover full chunks (all threads active)
        int v = tid + (it << 9);
        float4 a = rl4[v];
        PROC_CHUNK(a, v);
    }
    {   // partial vec chunk (no collectives; predicated pushes)
        int v = tid + (F << 9);
        if (v < nvec) {
            float4 a = rl4[v];
            sum0 += __expf(a.x); sum1 += __expf(a.y);
            sum2 += __expf(a.z); sum3 += __expf(a.w);
            unsigned base = (unsigned)(pre + 4 * v);
            if (a.x >= tau) { int p = atomicAdd(&s_cnt, 1); if (p < CAP) s_buf[p] = pack_key(a.x, base + 0); }
            if (a.y >= tau) { int p = atomicAdd(&s_cnt, 1); if (p < CAP) s_buf[p] = pack_key(a.y, base + 1); }
            if (a.z >= tau) { int p = atomicAdd(&s_cnt, 1); if (p < CAP) s_buf[p] = pack_key(a.z, base + 2); }
            if (a.w >= tau) { int p = atomicAdd(&s_cnt, 1); if (p < CAP) s_buf[p] = pack_key(a.w, base + 3); }
        }
    }
    {   // scalar tail (<=3 elements)
        int idx = tstart + tid;
        if (idx < NV) {
            float x = rl[idx];
            sum0 += __expf(x);
            if (x >= tau) {
                int p = atomicAdd(&s_cnt, 1);
                if (p < CAP) s_buf[p] = pack_key(x, (unsigned)idx);
            }
        }
    }

    // ---- Sum reduce -> logZ ----
    s_red[tid] = (sum0 + sum1) + (sum2 + sum3);
    __syncthreads();
#pragma unroll
    for (int s = 256; s > 0; s >>= 1) {
        if (tid < s) s_red[tid] += s_red[tid + s];
        __syncthreads();
    }
    float logZ = logf(s_red[0]);

    if (tid == 0) {
        float cs = cand_scores[row];
        g_row_c[row] = cs - logZ;
        g_eos[row]   = s_eosv - logZ + cs;
    }

    const int cnt = s_cnt;
    if (cnt <= CAP) {
        // remove EOS entry if it slipped in (tau guarantees >=8 non-EOS survivors)
        for (int i = tid; i < cnt; i += 512)
            if (key_low(s_buf[i]) == (unsigned)NEOS) s_buf[i] = 0;
        __syncthreads();
        // ---- Top-8 from candidate buffer: 8 block-argmax rounds ----
        for (int r = 0; r < 8; ++r) {
            unsigned long long my = 0;
            for (int i = tid; i < cnt; i += 512) {
                unsigned long long k = s_buf[i];
                if (k > my) my = k;
            }
            unsigned long long win = block_argmax(my, s_rs, tid);
            if (tid == 0) {
                g_top_val[row * 8 + r] = key_val(win);
                g_top_idx[row * 8 + r] = (int)key_low(win);
            }
            for (int i = tid; i < cnt; i += 512) {
                if (s_buf[i] == win) s_buf[i] = 0;
            }
            __syncthreads();
        }
    } else {
        // ---- Correct fallback (statistically never taken): per-thread sorted top-8 ----
        float tv[8]; int ti[8];
#pragma unroll
        for (int j = 0; j < 8; j++) { tv[j] = -CUDART_INF_F; ti[j] = 0x7FFFFFFF; }
        for (int v = tid; v < NV; v += 512) {
            if (v == NEOS) continue;
            float x = rl[v];
            if ((x > tv[7]) || (x == tv[7] && v < ti[7])) {
                tv[7] = x; ti[7] = v;
#pragma unroll
                for (int j = 7; j >= 1; --j) {
                    bool sw = (tv[j] > tv[j-1]) || (tv[j] == tv[j-1] && ti[j] < ti[j-1]);
                    float av = sw ? tv[j] : tv[j-1];
                    float bv = sw ? tv[j-1] : tv[j];
                    int ai = sw ? ti[j] : ti[j-1];
                    int bi = sw ? ti[j-1] : ti[j];
                    tv[j-1] = av; ti[j-1] = ai; tv[j] = bv; ti[j] = bi;
                }
            }
        }
        for (int r = 0; r < 8; ++r) {
            unsigned long long my = pack_key(tv[0], (unsigned)ti[0]);
            unsigned long long win = block_argmax(my, s_rs, tid);
            if (tid == 0) {
                g_top_val[row * 8 + r] = key_val(win);
                g_top_idx[row * 8 + r] = (int)key_low(win);
            }
            if (my == win) {
#pragma unroll
                for (int j = 0; j < 7; j++) { tv[j] = tv[j+1]; ti[j] = ti[j+1]; }
                tv[7] = -CUDART_INF_F; ti[7] = 0x7FFFFFFF;
            }
            __syncthreads();
        }
    }
}

// ---------------------------------------------------------------------------
// Kernel 2: one block per output row. Warp 0 re-derives the batch selection;
// warp 1 the completed-beam merge. Then the block writes row outputs + gathers.
// ---------------------------------------------------------------------------
__global__ __launch_bounds__(256) void k_epilogue(const int* __restrict__ cand_seqs,
                                                  const float* __restrict__ completed_scores,
                                                  const int* __restrict__ completed_seqs,
                                                  const int* __restrict__ completed_length,
                                                  const float* __restrict__ dctx,
                                                  const float* __restrict__ dr1,
                                                  const float* __restrict__ dr2,
                                                  float* __restrict__ out) {
    const int row = blockIdx.x;
    const int b = row >> 3, k = row & 7;
    const int t = threadIdx.x;

    __shared__ float s_selval[8]; __shared__ int s_selpar[8]; __shared__ int s_selsym[8];
    __shared__ float s_cscore[8]; __shared__ int s_clen[8]; __shared__ int s_cidx[8];

    if (t < 32) {
        // top-8 of the batch's 64 candidates via 8 warp-argmax rounds
        int l = t;
        float va = g_top_val[b * 64 + l]       + g_row_c[b * 8 + (l >> 3)];
        float vb = g_top_val[b * 64 + l + 32]  + g_row_c[b * 8 + ((l + 32) >> 3)];
        unsigned fa = (unsigned)((l >> 3) * NV + g_top_idx[b * 64 + l]);
        unsigned fb = (unsigned)(((l + 32) >> 3) * NV + g_top_idx[b * 64 + l + 32]);
        unsigned long long ka = pack_key(va, fa);
        unsigned long long kb = pack_key(vb, fb);
        for (int r = 0; r < 8; ++r) {
            unsigned long long my = (ka > kb) ? ka : kb;
            unsigned long long w = my;
#pragma unroll
            for (int off = 16; off; off >>= 1) {
                unsigned long long o = __shfl_xor_sync(0xFFFFFFFFu, w, off);
                if (o > w) w = o;
            }
            if (ka == w) ka = 0;
            if (kb == w) kb = 0;
            if (l == 0) {
                unsigned f = key_low(w);
                int par = (int)(f / (unsigned)NV);
                s_selval[r] = key_val(w);
                s_selpar[r] = par;
                s_selsym[r] = (int)(f - (unsigned)par * (unsigned)NV);
            }
        }
    } else if (t < 64) {
        // completed-beam merge: 16 candidates ranked by score/len (stable)
        int l = t - 32;
        float cs = 0.f; int cl = 1;
        unsigned long long key = 0;
        if (l < 16) {
            cs = (l < 8) ? completed_scores[b * 8 + l] : g_eos[b * 8 + (l - 8)];
            cl = (l < 8) ? completed_length[b * 8 + l] : (NL + 1);
            key = pack_key(cs / (float)cl, (unsigned)l);
        }
        for (int r = 0; r < 8; ++r) {
            unsigned long long w = key;
#pragma unroll
            for (int off = 16; off; off >>= 1) {
                unsigned long long o = __shfl_xor_sync(0xFFFFFFFFu, w, off);
                if (o > w) w = o;
            }
            if (key == w && key != 0) {
                s_cidx[r] = l; s_cscore[r] = cs; s_clen[r] = cl;
                key = 0;
            }
        }
    }
    __syncthreads();

    float* o_scores = out + OFF0;
    float* o_seqs   = out + OFF1;
    float* o_par    = out + OFF2;
    float* o_cscore = out + OFF3;
    float* o_cseqs  = out + OFF4;
    float* o_clen   = out + OFF5;

    const int par = s_selpar[k];
    const int ci  = s_cidx[k];

    if (t == 0) {
        o_scores[row] = s_selval[k];
        o_par[row]    = (float)par;
        o_cscore[row] = s_cscore[k];
        o_clen[row]   = (float)s_clen[k];
    }
    // new_seqs row (65 values)
    if (t < NL + 1) {
        int v = (t < NL) ? cand_seqs[(b * 8 + par) * NL + t] : s_selsym[k];
        o_seqs[row * (NL + 1) + t] = (float)v;
    }
    // comp_seqs row (128 values)
    if (t < NMAXL) {
        int v;
        if (ci < 8) v = completed_seqs[(b * 8 + ci) * NMAXL + t];
        else        v = (t < NL) ? cand_seqs[(b * 8 + (ci - 8)) * NL + t] : NEOS;
        o_cseqs[row * NMAXL + t] = (float)v;
    }

    // Parent-gather of decoder state (float4 copies)
    const int src = b * 8 + par;
    {
        const float4* s = (const float4*)(dctx + (size_t)src * NA);
        float4* d = (float4*)(out + OFF6 + (size_t)row * NA);
#pragma unroll
        for (int i = t; i < NA / 4; i += 256) d[i] = s[i];
    }
    {
        const float4* s = (const float4*)(dr1 + (size_t)src * ND);
        float4* d = (float4*)(out + OFF7 + (size_t)row * ND);
#pragma unroll
        for (int i = t; i < ND / 4; i += 256) d[i] = s[i];
    }
    {
        const float4* s = (const float4*)(dr2 + (size_t)src * ND);
        float4* d = (float4*)(out + OFF8 + (size_t)row * ND);
#pragma unroll
        for (int i = t; i < ND / 4; i += 256) d[i] = s[i];
    }
}

// ---------------------------------------------------------------------------
extern "C" void kernel_launch(void* const* d_in, const int* in_sizes, int n_in,
                              void* d_out, int out_size) {
    const float* logits            = (const float*)d_in[0];
    const float* cand_scores       = (const float*)d_in[1];
    const int*   cand_seqs         = (const int*)d_in[2];
    const float* completed_scores  = (const float*)d_in[3];
    const int*   completed_seqs    = (const int*)d_in[4];
    const int*   completed_length  = (const int*)d_in[5];
    const float* dctx              = (const float*)d_in[6];
    const float* dr1               = (const float*)d_in[7];
    const float* dr2               = (const float*)d_in[8];
    float* out = (float*)d_out;

    k_rows<<<ROWS, 512>>>(logits, cand_scores);
    k_epilogue<<<ROWS, 256>>>(cand_seqs, completed_scores, completed_seqs, completed_length,
                              dctx, dr1, dr2, out);
}

// round 8
// speedup vs baseline: 1.2808x; 1.2808x over previous
#include <cuda_runtime.h>
#include <math_constants.h>

// Problem constants
constexpr int NB = 128, NK = 8, NV = 50257, NL = 64, NMAXL = 128, NA = 512, ND = 1024;
constexpr int NEOS = 2;
constexpr int ROWS = NB * NK;   // 1024

// Output layout (single float32 dtype; integer outputs written as floats)
constexpr size_t OFF0 = 0;
constexpr size_t OFF1 = OFF0 + (size_t)NB * NK;
constexpr size_t OFF2 = OFF1 + (size_t)NB * NK * (NL + 1);
constexpr size_t OFF3 = OFF2 + (size_t)NB * NK;
constexpr size_t OFF4 = OFF3 + (size_t)NB * NK;
constexpr size_t OFF5 = OFF4 + (size_t)NB * NK * NMAXL;
constexpr size_t OFF6 = OFF5 + (size_t)NB * NK;
constexpr size_t OFF7 = OFF6 + (size_t)NB * NK * NA;
constexpr size_t OFF8 = OFF7 + (size_t)NB * NK * ND;

// Device scratch
__device__ float g_top_val[ROWS * 8];
__device__ int   g_top_idx[ROWS * 8];
__device__ float g_row_c[ROWS];
__device__ float g_eos[ROWS];

// Packed orderable key: larger == (larger val, then smaller idx). 0 = sentinel.
__device__ __forceinline__ unsigned long long pack_key(float v, unsigned int idx) {
    unsigned int u = __float_as_uint(v);
    u = (u & 0x80000000u) ? ~u : (u | 0x80000000u);
    return ((unsigned long long)u << 32) | (unsigned long long)(0xFFFFFFFFu - idx);
}
__device__ __forceinline__ float key_val(unsigned long long k) {
    unsigned int u = (unsigned int)(k >> 32);
    unsigned int bits = (u & 0x80000000u) ? (u ^ 0x80000000u) : ~u;
    return __uint_as_float(bits);
}
__device__ __forceinline__ unsigned key_low(unsigned long long k) {
    return 0xFFFFFFFFu - (unsigned int)(k & 0xFFFFFFFFu);
}

constexpr int CAP = 1024;

struct RedSmem {
    unsigned long long keys[16];
    unsigned long long win;
};

// Block-wide argmax over packed keys (512 threads). All threads must call.
__device__ __forceinline__ unsigned long long block_argmax(unsigned long long my,
                                                           RedSmem& rs, int tid) {
    int lane = tid & 31, wid = tid >> 5;
    unsigned long long k = my;
#pragma unroll
    for (int off = 16; off; off >>= 1) {
        unsigned long long o = __shfl_xor_sync(0xFFFFFFFFu, k, off);
        if (o > k) k = o;
    }
    if (lane == 0) rs.keys[wid] = k;
    __syncthreads();
    if (tid < 16) {
        unsigned long long kk = rs.keys[tid];
#pragma unroll
        for (int off = 8; off; off >>= 1) {
            unsigned long long o = __shfl_xor_sync(0x0000FFFFu, kk, off);
            if (o > kk) kk = o;
        }
        if (tid == 0) rs.win = kk;
    }
    __syncthreads();
    return rs.win;
}

// ---------------------------------------------------------------------------
// Kernel 1: per (b,k) row.
// Pass A: branch-free sumexp + per-thread running max over strided elements.
// tau = 9th-largest of the 512 thread maxima (ensures >=8 non-EOS elems >= tau,
// hence tau <= true non-EOS 8th-largest value).
// Pass B (cold, ~10 threads): re-read own elements, push x >= tau to smem.
// Extract stable top-8 from the tiny candidate buffer.
// ---------------------------------------------------------------------------
__global__ __launch_bounds__(512) void k_rows(const float* __restrict__ logits,
                                              const float* __restrict__ cand_scores) {
    const int row = blockIdx.x;
    const int tid = threadIdx.x;
    const float* rl = logits + (long long)row * NV;

    __shared__ unsigned long long s_buf[CAP];
    __shared__ float s_red[512];
    __shared__ RedSmem s_rs;
    __shared__ int s_cnt;
    __shared__ float s_tau;

    if (tid == 0) s_cnt = 0;

    // alignment peel (row base is only 4B aligned)
    const int pre = (int)(((16u - ((unsigned)(unsigned long long)rl & 15u)) & 15u) >> 2);
    const int nvec = (NV - pre) >> 2;
    const int tstart = pre + nvec * 4;
    const float4* rl4 = (const float4*)(rl + pre);

    // ---- Pass A: branch-free scan (no votes, no atomics, no data branches) ----
    float sum0 = 0.f, sum1 = 0.f, sum2 = 0.f, sum3 = 0.f;
    float mymax = -CUDART_INF_F;

    if (tid < pre) {
        float x = rl[tid];
        sum0 += __expf(x);
        mymax = fmaxf(mymax, x);
    }
#pragma unroll 4
    for (int v = tid; v < nvec; v += 512) {
        float4 q = rl4[v];
        sum0 += __expf(q.x);
        sum1 += __expf(q.y);
        sum2 += __expf(q.z);
        sum3 += __expf(q.w);
        mymax = fmaxf(mymax, fmaxf(fmaxf(q.x, q.y), fmaxf(q.z, q.w)));
    }
    {
        int idx = tstart + tid;
        if (idx < NV) {
            float x = rl[idx];
            sum0 += __expf(x);
            mymax = fmaxf(mymax, x);
        }
    }

    // ---- Sum reduce -> logZ ----
    s_red[tid] = (sum0 + sum1) + (sum2 + sum3);
    __syncthreads();
#pragma unroll
    for (int s = 256; s > 0; s >>= 1) {
        if (tid < s) s_red[tid] += s_red[tid + s];
        __syncthreads();
    }
    float logZ = logf(s_red[0]);

    if (tid == 0) {
        float cs = cand_scores[row];
        g_row_c[row] = cs - logZ;
        g_eos[row]   = rl[NEOS] - logZ + cs;   // L2/L1 hit
    }

    // ---- tau = 9th-largest per-thread max (9 block-argmax rounds) ----
    {
        unsigned long long mk = pack_key(mymax, (unsigned)tid);
        unsigned long long win = 0;
        for (int r = 0; r < 9; ++r) {
            win = block_argmax(mk, s_rs, tid);
            if (mk == win) mk = 0;
        }
        if (tid == 0) s_tau = key_val(win);
        __syncthreads();
    }
    const float tau = s_tau;

    // ---- Pass B (cold): only threads whose max reaches tau re-scan their own
    //      elements; addresses are L2-resident. No collectives here.
    if (mymax >= tau) {
        if (tid < pre) {
            float x = rl[tid];
            if (x >= tau) { int p = atomicAdd(&s_cnt, 1); if (p < CAP) s_buf[p] = pack_key(x, (unsigned)tid); }
        }
        for (int v = tid; v < nvec; v += 512) {
            float4 q = rl4[v];
            float mm = fmaxf(fmaxf(q.x, q.y), fmaxf(q.z, q.w));
            if (mm >= tau) {
                unsigned base = (unsigned)(pre + 4 * v);
                if (q.x >= tau) { int p = atomicAdd(&s_cnt, 1); if (p < CAP) s_buf[p] = pack_key(q.x, base + 0); }
                if (q.y >= tau) { int p = atomicAdd(&s_cnt, 1); if (p < CAP) s_buf[p] = pack_key(q.y, base + 1); }
                if (q.z >= tau) { int p = atomicAdd(&s_cnt, 1); if (p < CAP) s_buf[p] = pack_key(q.z, base + 2); }
                if (q.w >= tau) { int p = atomicAdd(&s_cnt, 1); if (p < CAP) s_buf[p] = pack_key(q.w, base + 3); }
            }
        }
        {
            int idx = tstart + tid;
            if (idx < NV) {
                float x = rl[idx];
                if (x >= tau) { int p = atomicAdd(&s_cnt, 1); if (p < CAP) s_buf[p] = pack_key(x, (unsigned)idx); }
            }
        }
    }
    __syncthreads();

    const int cnt = s_cnt;
    if (cnt <= CAP) {
        // remove EOS entry if present (tau construction guarantees >=8 non-EOS)
        for (int i = tid; i < cnt; i += 512)
            if (key_low(s_buf[i]) == (unsigned)NEOS) s_buf[i] = 0;
        __syncthreads();
        // ---- Top-8 from the tiny candidate buffer: 8 block-argmax rounds ----
        for (int r = 0; r < 8; ++r) {
            unsigned long long my = 0;
            for (int i = tid; i < cnt; i += 512) {
                unsigned long long k = s_buf[i];
                if (k > my) my = k;
            }
            unsigned long long win = block_argmax(my, s_rs, tid);
            if (tid == 0) {
                g_top_val[row * 8 + r] = key_val(win);
                g_top_idx[row * 8 + r] = (int)key_low(win);
            }
            for (int i = tid; i < cnt; i += 512) {
                if (s_buf[i] == win) s_buf[i] = 0;
            }
            __syncthreads();
        }
    } else {
        // ---- Exact fallback (degenerate/tied distributions only) ----
        float tv[8]; int ti[8];
#pragma unroll
        for (int j = 0; j < 8; j++) { tv[j] = -CUDART_INF_F; ti[j] = 0x7FFFFFFF; }
        for (int v = tid; v < NV; v += 512) {
            if (v == NEOS) continue;
            float x = rl[v];
            if ((x > tv[7]) || (x == tv[7] && v < ti[7])) {
                tv[7] = x; ti[7] = v;
#pragma unroll
                for (int j = 7; j >= 1; --j) {
                    bool sw = (tv[j] > tv[j-1]) || (tv[j] == tv[j-1] && ti[j] < ti[j-1]);
                    float av = sw ? tv[j] : tv[j-1];
                    float bv = sw ? tv[j-1] : tv[j];
                    int ai = sw ? ti[j] : ti[j-1];
                    int bi = sw ? ti[j-1] : ti[j];
                    tv[j-1] = av; ti[j-1] = ai; tv[j] = bv; ti[j] = bi;
                }
            }
        }
        for (int r = 0; r < 8; ++r) {
            unsigned long long my = pack_key(tv[0], (unsigned)ti[0]);
            unsigned long long win = block_argmax(my, s_rs, tid);
            if (tid == 0) {
                g_top_val[row * 8 + r] = key_val(win);
                g_top_idx[row * 8 + r] = (int)key_low(win);
            }
            if (my == win) {
#pragma unroll
                for (int j = 0; j < 7; j++) { tv[j] = tv[j+1]; ti[j] = ti[j+1]; }
                tv[7] = -CUDART_INF_F; ti[7] = 0x7FFFFFFF;
            }
            __syncthreads();
        }
    }
}

// ---------------------------------------------------------------------------
// Kernel 2: one block per output row. Warp 0 re-derives the batch selection;
// warp 1 the completed-beam merge. Then the block writes row outputs + gathers.
// ---------------------------------------------------------------------------
__global__ __launch_bounds__(256) void k_epilogue(const int* __restrict__ cand_seqs,
                                                  const float* __restrict__ completed_scores,
                                                  const int* __restrict__ completed_seqs,
                                                  const int* __restrict__ completed_length,
                                                  const float* __restrict__ dctx,
                                                  const float* __restrict__ dr1,
                                                  const float* __restrict__ dr2,
                                                  float* __restrict__ out) {
    const int row = blockIdx.x;
    const int b = row >> 3, k = row & 7;
    const int t = threadIdx.x;

    __shared__ float s_selval[8]; __shared__ int s_selpar[8]; __shared__ int s_selsym[8];
    __shared__ float s_cscore[8]; __shared__ int s_clen[8]; __shared__ int s_cidx[8];

    if (t < 32) {
        // top-8 of the batch's 64 candidates via 8 warp-argmax rounds
        int l = t;
        float va = g_top_val[b * 64 + l]       + g_row_c[b * 8 + (l >> 3)];
        float vb = g_top_val[b * 64 + l + 32]  + g_row_c[b * 8 + ((l + 32) >> 3)];
        unsigned fa = (unsigned)((l >> 3) * NV + g_top_idx[b * 64 + l]);
        unsigned fb = (unsigned)(((l + 32) >> 3) * NV + g_top_idx[b * 64 + l + 32]);
        unsigned long long ka = pack_key(va, fa);
        unsigned long long kb = pack_key(vb, fb);
        for (int r = 0; r < 8; ++r) {
            unsigned long long my = (ka > kb) ? ka : kb;
            unsigned long long w = my;
#pragma unroll
            for (int off = 16; off; off >>= 1) {
                unsigned long long o = __shfl_xor_sync(0xFFFFFFFFu, w, off);
                if (o > w) w = o;
            }
            if (ka == w) ka = 0;
            if (kb == w) kb = 0;
            if (l == 0) {
                unsigned f = key_low(w);
                int par = (int)(f / (unsigned)NV);
                s_selval[r] = key_val(w);
                s_selpar[r] = par;
                s_selsym[r] = (int)(f - (unsigned)par * (unsigned)NV);
            }
        }
    } else if (t < 64) {
        // completed-beam merge: 16 candidates ranked by score/len (stable)
        int l = t - 32;
        float cs = 0.f; int cl = 1;
        unsigned long long key = 0;
        if (l < 16) {
            cs = (l < 8) ? completed_scores[b * 8 + l] : g_eos[b * 8 + (l - 8)];
            cl = (l < 8) ? completed_length[b * 8 + l] : (NL + 1);
            key = pack_key(cs / (float)cl, (unsigned)l);
        }
        for (int r = 0; r < 8; ++r) {
            unsigned long long w = key;
#pragma unroll
            for (int off = 16; off; off >>= 1) {
                unsigned long long o = __shfl_xor_sync(0xFFFFFFFFu, w, off);
                if (o > w) w = o;
            }
            if (key == w && key != 0) {
                s_cidx[r] = l; s_cscore[r] = cs; s_clen[r] = cl;
                key = 0;
            }
        }
    }
    __syncthreads();

    float* o_scores = out + OFF0;
    float* o_seqs   = out + OFF1;
    float* o_par    = out + OFF2;
    float* o_cscore = out + OFF3;
    float* o_cseqs  = out + OFF4;
    float* o_clen   = out + OFF5;

    const int par = s_selpar[k];
    const int ci  = s_cidx[k];

    if (t == 0) {
        o_scores[row] = s_selval[k];
        o_par[row]    = (float)par;
        o_cscore[row] = s_cscore[k];
        o_clen[row]   = (float)s_clen[k];
    }
    // new_seqs row (65 values)
    if (t < NL + 1) {
        int v = (t < NL) ? cand_seqs[(b * 8 + par) * NL + t] : s_selsym[k];
        o_seqs[row * (NL + 1) + t] = (float)v;
    }
    // comp_seqs row (128 values)
    if (t < NMAXL) {
        int v;
        if (ci < 8) v = completed_seqs[(b * 8 + ci) * NMAXL + t];
        else        v = (t < NL) ? cand_seqs[(b * 8 + (ci - 8)) * NL + t] : NEOS;
        o_cseqs[row * NMAXL + t] = (float)v;
    }

    // Parent-gather of decoder state (float4 copies)
    const int src = b * 8 + par;
    {
        const float4* s = (const float4*)(dctx + (size_t)src * NA);
        float4* d = (float4*)(out + OFF6 + (size_t)row * NA);
#pragma unroll
        for (int i = t; i < NA / 4; i += 256) d[i] = s[i];
    }
    {
        const float4* s = (const float4*)(dr1 + (size_t)src * ND);
        float4* d = (float4*)(out + OFF7 + (size_t)row * ND);
#pragma unroll
        for (int i = t; i < ND / 4; i += 256) d[i] = s[i];
    }
    {
        const float4* s = (const float4*)(dr2 + (size_t)src * ND);
        float4* d = (float4*)(out + OFF8 + (size_t)row * ND);
#pragma unroll
        for (int i = t; i < ND / 4; i += 256) d[i] = s[i];
    }
}

// ---------------------------------------------------------------------------
extern "C" void kernel_launch(void* const* d_in, const int* in_sizes, int n_in,
                              void* d_out, int out_size) {
    const float* logits            = (const float*)d_in[0];
    const float* cand_scores       = (const float*)d_in[1];
    const int*   cand_seqs         = (const int*)d_in[2];
    const float* completed_scores  = (const float*)d_in[3];
    const int*   completed_seqs    = (const int*)d_in[4];
    const int*   completed_length  = (const int*)d_in[5];
    const float* dctx              = (const float*)d_in[6];
    const float* dr1               = (const float*)d_in[7];
    const float* dr2               = (const float*)d_in[8];
    float* out = (float*)d_out;

    k_rows<<<ROWS, 512>>>(logits, cand_scores);
    k_epilogue<<<ROWS, 256>>>(cand_seqs, completed_scores, completed_seqs, completed_length,
                              dctx, dr1, dr2, out);
}

// round 9
// speedup vs baseline: 1.2864x; 1.0044x over previous
#include <cuda_runtime.h>
#include <math_constants.h>

// Problem constants
constexpr int NB = 128, NK = 8, NV = 50257, NL = 64, NMAXL = 128, NA = 512, ND = 1024;
constexpr int NEOS = 2;
constexpr int ROWS = NB * NK;   // 1024

// Output layout (single float32 dtype; integer outputs written as floats)
constexpr size_t OFF0 = 0;
constexpr size_t OFF1 = OFF0 + (size_t)NB * NK;
constexpr size_t OFF2 = OFF1 + (size_t)NB * NK * (NL + 1);
constexpr size_t OFF3 = OFF2 + (size_t)NB * NK;
constexpr size_t OFF4 = OFF3 + (size_t)NB * NK;
constexpr size_t OFF5 = OFF4 + (size_t)NB * NK * NMAXL;
constexpr size_t OFF6 = OFF5 + (size_t)NB * NK;
constexpr size_t OFF7 = OFF6 + (size_t)NB * NK * NA;
constexpr size_t OFF8 = OFF7 + (size_t)NB * NK * ND;

// Device scratch
__device__ float g_top_val[ROWS * 8];
__device__ int   g_top_idx[ROWS * 8];
__device__ float g_row_c[ROWS];
__device__ float g_eos[ROWS];

// Packed orderable key: larger == (larger val, then smaller idx). 0 = sentinel.
__device__ __forceinline__ unsigned long long pack_key(float v, unsigned int idx) {
    unsigned int u = __float_as_uint(v);
    u = (u & 0x80000000u) ? ~u : (u | 0x80000000u);
    return ((unsigned long long)u << 32) | (unsigned long long)(0xFFFFFFFFu - idx);
}
__device__ __forceinline__ float key_val(unsigned long long k) {
    unsigned int u = (unsigned int)(k >> 32);
    unsigned int bits = (u & 0x80000000u) ? (u ^ 0x80000000u) : ~u;
    return __uint_as_float(bits);
}
__device__ __forceinline__ unsigned key_low(unsigned long long k) {
    return 0xFFFFFFFFu - (unsigned int)(k & 0xFFFFFFFFu);
}

constexpr int CAPC = 1024;   // chunk buffer
constexpr int CAPE = 1024;   // element buffer

struct RedSmem {
    unsigned long long keys[16];
    unsigned long long win;
};

// Block-wide argmax over packed keys (512 threads). All threads must call.
__device__ __forceinline__ unsigned long long block_argmax(unsigned long long my,
                                                           RedSmem& rs, int tid) {
    int lane = tid & 31, wid = tid >> 5;
    unsigned long long k = my;
#pragma unroll
    for (int off = 16; off; off >>= 1) {
        unsigned long long o = __shfl_xor_sync(0xFFFFFFFFu, k, off);
        if (o > k) k = o;
    }
    if (lane == 0) rs.keys[wid] = k;
    __syncthreads();
    if (tid < 16) {
        unsigned long long kk = rs.keys[tid];
#pragma unroll
        for (int off = 8; off; off >>= 1) {
            unsigned long long o = __shfl_xor_sync(0x0000FFFFu, kk, off);
            if (o > kk) kk = o;
        }
        if (tid == 0) rs.win = kk;
    }
    __syncthreads();
    return rs.win;
}

__device__ __forceinline__ float max4(float4 q) {
    return fmaxf(fmaxf(q.x, q.y), fmaxf(q.z, q.w));
}

// ---------------------------------------------------------------------------
// Kernel 1: per (b,k) row.
//  Presample: tau = 8th-largest of 512 per-thread maxima over first 4096 elems
//             (EOS excluded) => tau <= true non-EOS 8th-largest row value.
//  Pass A:    branch-free sumexp + chunk-max; rare (one per 4 chunks) branch
//             pushes flagged CHUNK indices to smem.
//  Pass B:    one parallel round converts ~100 flagged chunks to elements.
//  Extract:   stable top-8 from the tiny element buffer.
// ---------------------------------------------------------------------------
__global__ __launch_bounds__(512) void k_rows(const float* __restrict__ logits,
                                              const float* __restrict__ cand_scores) {
    const int row = blockIdx.x;
    const int tid = threadIdx.x;
    const float* rl = logits + (long long)row * NV;

    __shared__ int s_chunk[CAPC];
    __shared__ unsigned long long s_buf[CAPE];
    __shared__ float s_red[512];
    __shared__ RedSmem s_rs;
    __shared__ int s_cnt;     // chunk count
    __shared__ int s_ecnt;    // element count
    __shared__ float s_eosv;
    __shared__ float s_tau;

    if (tid == 0) { s_cnt = 0; s_ecnt = 0; }

    // alignment peel (row base is only 4B aligned)
    const int pre = (int)(((16u - ((unsigned)(unsigned long long)rl & 15u)) & 15u) >> 2);
    const int nvec = (NV - pre) >> 2;
    const int tstart = pre + nvec * 4;
    const float4* rl4 = (const float4*)(rl + pre);

    // ---- Presample: tau over first 4096 elements ----
    {
        float m = -CUDART_INF_F;
#pragma unroll
        for (int i = 0; i < 8; ++i) {
            int idx = i * 512 + tid;
            float x = rl[idx];
            if (idx == NEOS) { s_eosv = x; x = -CUDART_INF_F; }
            m = fmaxf(m, x);
        }
        unsigned long long mk = pack_key(m, (unsigned)tid);
        unsigned long long win = 0;
        for (int r = 0; r < 8; ++r) {
            win = block_argmax(mk, s_rs, tid);
            if (mk == win) mk = 0;
        }
        if (tid == 0) s_tau = key_val(win);
        __syncthreads();
    }
    const float tau = s_tau;

    // ---- Pass A: sumexp + flagged-chunk collection ----
    float sum0 = 0.f, sum1 = 0.f, sum2 = 0.f, sum3 = 0.f;

    {   // scalar peel (<=3 elements): direct element pushes (EOS excluded)
        if (tid < pre) {
            float x = rl[tid];
            sum0 += __expf(x);
            if (x >= tau && tid != NEOS) {
                int p = atomicAdd(&s_ecnt, 1);
                if (p < CAPE) s_buf[p] = pack_key(x, (unsigned)tid);
            }
        }
    }

    int v = tid;
    for (; v + 1536 < nvec; v += 2048) {
        float4 a = rl4[v];
        float4 b = rl4[v + 512];
        float4 c = rl4[v + 1024];
        float4 d = rl4[v + 1536];
        sum0 += __expf(a.x); sum1 += __expf(a.y); sum2 += __expf(a.z); sum3 += __expf(a.w);
        sum0 += __expf(b.x); sum1 += __expf(b.y); sum2 += __expf(b.z); sum3 += __expf(b.w);
        sum0 += __expf(c.x); sum1 += __expf(c.y); sum2 += __expf(c.z); sum3 += __expf(c.w);
        sum0 += __expf(d.x); sum1 += __expf(d.y); sum2 += __expf(d.z); sum3 += __expf(d.w);
        float m0 = max4(a), m1 = max4(b), m2 = max4(c), m3 = max4(d);
        float g = fmaxf(fmaxf(m0, m1), fmaxf(m2, m3));
        if (g >= tau) {   // rare (~3%): push flagged chunk indices
            if (m0 >= tau) { int p = atomicAdd(&s_cnt, 1); if (p < CAPC) s_chunk[p] = v; }
            if (m1 >= tau) { int p = atomicAdd(&s_cnt, 1); if (p < CAPC) s_chunk[p] = v + 512; }
            if (m2 >= tau) { int p = atomicAdd(&s_cnt, 1); if (p < CAPC) s_chunk[p] = v + 1024; }
            if (m3 >= tau) { int p = atomicAdd(&s_cnt, 1); if (p < CAPC) s_chunk[p] = v + 1536; }
        }
    }
    for (; v < nvec; v += 512) {   // leftover single chunks
        float4 a = rl4[v];
        sum0 += __expf(a.x); sum1 += __expf(a.y); sum2 += __expf(a.z); sum3 += __expf(a.w);
        if (max4(a) >= tau) { int p = atomicAdd(&s_cnt, 1); if (p < CAPC) s_chunk[p] = v; }
    }
    {   // scalar tail (<=3 elements)
        int idx = tstart + tid;
        if (idx < NV) {
            float x = rl[idx];
            sum0 += __expf(x);
            if (x >= tau) {
                int p = atomicAdd(&s_ecnt, 1);
                if (p < CAPE) s_buf[p] = pack_key(x, (unsigned)idx);
            }
        }
    }

    // ---- Sum reduce -> logZ ----
    s_red[tid] = (sum0 + sum1) + (sum2 + sum3);
    __syncthreads();
#pragma unroll
    for (int s = 256; s > 0; s >>= 1) {
        if (tid < s) s_red[tid] += s_red[tid + s];
        __syncthreads();
    }
    float logZ = logf(s_red[0]);

    if (tid == 0) {
        float cs = cand_scores[row];
        g_row_c[row] = cs - logZ;
        g_eos[row]   = s_eosv - logZ + cs;
    }

    // ---- Pass B: flagged chunks -> elements (one parallel round) ----
    const int ccnt = s_cnt;
    const bool chunks_ok = (ccnt <= CAPC);
    if (chunks_ok) {
        for (int i = tid; i < ccnt; i += 512) {
            int cv = s_chunk[i];
            float4 q = rl4[cv];
            unsigned base = (unsigned)(pre + 4 * cv);
            if (q.x >= tau && base + 0 != (unsigned)NEOS) { int p = atomicAdd(&s_ecnt, 1); if (p < CAPE) s_buf[p] = pack_key(q.x, base + 0); }
            if (q.y >= tau && base + 1 != (unsigned)NEOS) { int p = atomicAdd(&s_ecnt, 1); if (p < CAPE) s_buf[p] = pack_key(q.y, base + 1); }
            if (q.z >= tau && base + 2 != (unsigned)NEOS) { int p = atomicAdd(&s_ecnt, 1); if (p < CAPE) s_buf[p] = pack_key(q.z, base + 2); }
            if (q.w >= tau && base + 3 != (unsigned)NEOS) { int p = atomicAdd(&s_ecnt, 1); if (p < CAPE) s_buf[p] = pack_key(q.w, base + 3); }
        }
    }
    __syncthreads();

    const int ecnt = s_ecnt;
    if (chunks_ok && ecnt <= CAPE) {
        // ---- Top-8 from the tiny element buffer: 8 block-argmax rounds ----
        for (int r = 0; r < 8; ++r) {
            unsigned long long my = 0;
            for (int i = tid; i < ecnt; i += 512) {
                unsigned long long k = s_buf[i];
                if (k > my) my = k;
            }
            unsigned long long win = block_argmax(my, s_rs, tid);
            if (tid == 0) {
                g_top_val[row * 8 + r] = key_val(win);
                g_top_idx[row * 8 + r] = (int)key_low(win);
            }
            for (int i = tid; i < ecnt; i += 512) {
                if (s_buf[i] == win) s_buf[i] = 0;
            }
            __syncthreads();
        }
    } else {
        // ---- Exact fallback (degenerate/tied distributions only) ----
        float tv[8]; int ti[8];
#pragma unroll
        for (int j = 0; j < 8; j++) { tv[j] = -CUDART_INF_F; ti[j] = 0x7FFFFFFF; }
        for (int vv = tid; vv < NV; vv += 512) {
            if (vv == NEOS) continue;
            float x = rl[vv];
            if ((x > tv[7]) || (x == tv[7] && vv < ti[7])) {
                tv[7] = x; ti[7] = vv;
#pragma unroll
                for (int j = 7; j >= 1; --j) {
                    bool sw = (tv[j] > tv[j-1]) || (tv[j] == tv[j-1] && ti[j] < ti[j-1]);
                    float av = sw ? tv[j] : tv[j-1];
                    float bv = sw ? tv[j-1] : tv[j];
                    int ai = sw ? ti[j] : ti[j-1];
                    int bi = sw ? ti[j-1] : ti[j];
                    tv[j-1] = av; ti[j-1] = ai; tv[j] = bv; ti[j] = bi;
                }
            }
        }
        for (int r = 0; r < 8; ++r) {
            unsigned long long my = pack_key(tv[0], (unsigned)ti[0]);
            unsigned long long win = block_argmax(my, s_rs, tid);
            if (tid == 0) {
                g_top_val[row * 8 + r] = key_val(win);
                g_top_idx[row * 8 + r] = (int)key_low(win);
            }
            if (my == win) {
#pragma unroll
                for (int j = 0; j < 7; j++) { tv[j] = tv[j+1]; ti[j] = ti[j+1]; }
                tv[7] = -CUDART_INF_F; ti[7] = 0x7FFFFFFF;
            }
            __syncthreads();
        }
    }
}

// ---------------------------------------------------------------------------
// Kernel 2: one block per output row; NO block barriers. Every warp redundantly
// derives the batch selection (8 warp-argmax rounds). Warp 0 writes scalars +
// new_seqs, warp 1 does the completed merge + comp outputs, all warps gather.
// ---------------------------------------------------------------------------
__global__ __launch_bounds__(256) void k_epilogue(const int* __restrict__ cand_seqs,
                                                  const float* __restrict__ completed_scores,
                                                  const int* __restrict__ completed_seqs,
                                                  const int* __restrict__ completed_length,
                                                  const float* __restrict__ dctx,
                                                  const float* __restrict__ dr1,
                                                  const float* __restrict__ dr2,
                                                  float* __restrict__ out) {
    const int row = blockIdx.x;
    const int b = row >> 3, k = row & 7;
    const int t = threadIdx.x;
    const int lane = t & 31, wrp = t >> 5;

    // --- every warp: selection over the batch's 64 candidates ---
    float va = g_top_val[b * 64 + lane]      + g_row_c[b * 8 + (lane >> 3)];
    float vb = g_top_val[b * 64 + lane + 32] + g_row_c[b * 8 + ((lane + 32) >> 3)];
    unsigned fa = (unsigned)((lane >> 3) * NV + g_top_idx[b * 64 + lane]);
    unsigned fb = (unsigned)(((lane + 32) >> 3) * NV + g_top_idx[b * 64 + lane + 32]);
    unsigned long long ka = pack_key(va, fa);
    unsigned long long kb = pack_key(vb, fb);
    float selval = 0.f; int par = 0, sym = 0;
    for (int r = 0; r < 8; ++r) {
        unsigned long long w = (ka > kb) ? ka : kb;
#pragma unroll
        for (int off = 16; off; off >>= 1) {
            unsigned long long o = __shfl_xor_sync(0xFFFFFFFFu, w, off);
            if (o > w) w = o;
        }
        if (ka == w) ka = 0;
        if (kb == w) kb = 0;
        if (r == k) {   // this row's beam slot (warp-uniform)
            unsigned f = key_low(w);
            par = (int)(f / (unsigned)NV);
            sym = (int)(f - (unsigned)par * (unsigned)NV);
            selval = key_val(w);
        }
    }

    float* o_scores = out + OFF0;
    float* o_seqs   = out + OFF1;
    float* o_par    = out + OFF2;
    float* o_cscore = out + OFF3;
    float* o_cseqs  = out + OFF4;
    float* o_clen   = out + OFF5;

    if (wrp == 0) {
        // scalar outputs + new_seqs row (65 values)
        if (lane == 0) {
            o_scores[row] = selval;
            o_par[row]    = (float)par;
        }
        for (int p = lane; p < NL + 1; p += 32) {
            int vv = (p < NL) ? cand_seqs[(b * 8 + par) * NL + p] : sym;
            o_seqs[row * (NL + 1) + p] = (float)vv;
        }
    } else if (wrp == 1) {
        // completed-beam merge: 16 candidates ranked by score/len (stable)
        float cs = 0.f; int cl = 1;
        unsigned long long key = 0;
        if (lane < 16) {
            cs = (lane < 8) ? completed_scores[b * 8 + lane] : g_eos[b * 8 + (lane - 8)];
            cl = (lane < 8) ? completed_length[b * 8 + lane] : (NL + 1);
            key = pack_key(cs / (float)cl, (unsigned)lane);
        }
        int ci = 0;
        for (int r = 0; r < 8; ++r) {
            unsigned long long w = key;
#pragma unroll
            for (int off = 16; off; off >>= 1) {
                unsigned long long o = __shfl_xor_sync(0xFFFFFFFFu, w, off);
                if (o > w) w = o;
            }
            if (key == w && key != 0) key = 0;
            if (r == k) ci = (int)key_low(w);   // warp-uniform
        }
        float cscore = __shfl_sync(0xFFFFFFFFu, cs, ci);
        int   clen   = __shfl_sync(0xFFFFFFFFu, cl, ci);
        if (lane == 0) {
            o_cscore[row] = cscore;
            o_clen[row]   = (float)clen;
        }
        for (int p = lane; p < NMAXL; p += 32) {
            int vv;
            if (ci < 8) vv = completed_seqs[(b * 8 + ci) * NMAXL + p];
            else        vv = (p < NL) ? cand_seqs[(b * 8 + (ci - 8)) * NL + p] : NEOS;
            o_cseqs[row * NMAXL + p] = (float)vv;
        }
    }

    // --- all warps: parent-gather of decoder state (float4 copies) ---
    const int src = b * 8 + par;
    {
        const float4* s = (const float4*)(dctx + (size_t)src * NA);
        float4* d = (float4*)(out + OFF6 + (size_t)row * NA);
#pragma unroll
        for (int i = t; i < NA / 4; i += 256) d[i] = s[i];
    }
    {
        const float4* s = (const float4*)(dr1 + (size_t)src * ND);
        float4* d = (float4*)(out + OFF7 + (size_t)row * ND);
#pragma unroll
        for (int i = t; i < ND / 4; i += 256) d[i] = s[i];
    }
    {
        const float4* s = (const float4*)(dr2 + (size_t)src * ND);
        float4* d = (float4*)(out + OFF8 + (size_t)row * ND);
#pragma unroll
        for (int i = t; i < ND / 4; i += 256) d[i] = s[i];
    }
}

// ---------------------------------------------------------------------------
extern "C" void kernel_launch(void* const* d_in, const int* in_sizes, int n_in,
                              void* d_out, int out_size) {
    const float* logits            = (const float*)d_in[0];
    const float* cand_scores       = (const float*)d_in[1];
    const int*   cand_seqs         = (const int*)d_in[2];
    const float* completed_scores  = (const float*)d_in[3];
    const int*   completed_seqs    = (const int*)d_in[4];
    const int*   completed_length  = (const int*)d_in[5];
    const float* dctx              = (const float*)d_in[6];
    const float* dr1               = (const float*)d_in[7];
    const float* dr2               = (const float*)d_in[8];
    float* out = (float*)d_out;

    k_rows<<<ROWS, 512>>>(logits, cand_scores);
    k_epilogue<<<ROWS, 256>>>(cand_seqs, completed_scores, completed_seqs, completed_length,
                              dctx, dr1, dr2, out);
}

// round 10
// speedup vs baseline: 1.3763x; 1.0699x over previous
#include <cuda_runtime.h>
#include <math_constants.h>

// Problem constants
constexpr int NB = 128, NK = 8, NV = 50257, NL = 64, NMAXL = 128, NA = 512, ND = 1024;
constexpr int NEOS = 2;
constexpr int ROWS = NB * NK;   // 1024

// Output layout (single float32 dtype; integer outputs written as floats)
constexpr size_t OFF0 = 0;
constexpr size_t OFF1 = OFF0 + (size_t)NB * NK;
constexpr size_t OFF2 = OFF1 + (size_t)NB * NK * (NL + 1);
constexpr size_t OFF3 = OFF2 + (size_t)NB * NK;
constexpr size_t OFF4 = OFF3 + (size_t)NB * NK;
constexpr size_t OFF5 = OFF4 + (size_t)NB * NK * NMAXL;
constexpr size_t OFF6 = OFF5 + (size_t)NB * NK;
constexpr size_t OFF7 = OFF6 + (size_t)NB * NK * NA;
constexpr size_t OFF8 = OFF7 + (size_t)NB * NK * ND;

// Device scratch
__device__ float g_top_val[ROWS * 8];
__device__ int   g_top_idx[ROWS * 8];
__device__ float g_row_c[ROWS];
__device__ float g_eos[ROWS];

// Packed orderable key: larger == (larger val, then smaller idx). 0 = sentinel.
__device__ __forceinline__ unsigned long long pack_key(float v, unsigned int idx) {
    unsigned int u = __float_as_uint(v);
    u = (u & 0x80000000u) ? ~u : (u | 0x80000000u);
    return ((unsigned long long)u << 32) | (unsigned long long)(0xFFFFFFFFu - idx);
}
__device__ __forceinline__ float key_val(unsigned long long k) {
    unsigned int u = (unsigned int)(k >> 32);
    unsigned int bits = (u & 0x80000000u) ? (u ^ 0x80000000u) : ~u;
    return __uint_as_float(bits);
}
__device__ __forceinline__ unsigned key_low(unsigned long long k) {
    return 0xFFFFFFFFu - (unsigned int)(k & 0xFFFFFFFFu);
}

constexpr int CAPC = 1024;   // chunk buffer
constexpr int CAPE = 1024;   // element buffer

struct RedSmem {
    unsigned long long keys[16];
    unsigned long long win;
};

// Block-wide argmax over packed keys (512 threads). All threads must call.
__device__ __forceinline__ unsigned long long block_argmax(unsigned long long my,
                                                           RedSmem& rs, int tid) {
    int lane = tid & 31, wid = tid >> 5;
    unsigned long long k = my;
#pragma unroll
    for (int off = 16; off; off >>= 1) {
        unsigned long long o = __shfl_xor_sync(0xFFFFFFFFu, k, off);
        if (o > k) k = o;
    }
    if (lane == 0) rs.keys[wid] = k;
    __syncthreads();
    if (tid < 16) {
        unsigned long long kk = rs.keys[tid];
#pragma unroll
        for (int off = 8; off; off >>= 1) {
            unsigned long long o = __shfl_xor_sync(0x0000FFFFu, kk, off);
            if (o > kk) kk = o;
        }
        if (tid == 0) rs.win = kk;
    }
    __syncthreads();
    return rs.win;
}

__device__ __forceinline__ float max4(float4 q) {
    return fmaxf(fmaxf(q.x, q.y), fmaxf(q.z, q.w));
}

// ---------------------------------------------------------------------------
// Kernel 0: no-op (shifts ncu's -s 5 capture onto k_rows; removed later)
// ---------------------------------------------------------------------------
__global__ void k_nop() {}

// ---------------------------------------------------------------------------
// Kernel 1: per (b,k) row.
//  Presample: tau = 8th-largest of 512 per-thread maxima over first 4096 elems
//             (EOS excluded) => tau <= true non-EOS 8th-largest row value.
//  Pass A:    SOFTWARE-PIPELINED branch-free sumexp + chunk-max; group i+1's
//             loads issue before group i is processed (continuous MLP=4).
//             One rare branch per 4 chunks pushes flagged CHUNK indices.
//  Pass B:    one parallel round converts flagged chunks to elements.
//  Extract:   stable top-8 from the tiny element buffer.
// ---------------------------------------------------------------------------
__global__ __launch_bounds__(512) void k_rows(const float* __restrict__ logits,
                                              const float* __restrict__ cand_scores) {
    const int row = blockIdx.x;
    const int tid = threadIdx.x;
    const float* rl = logits + (long long)row * NV;

    __shared__ int s_chunk[CAPC];
    __shared__ unsigned long long s_buf[CAPE];
    __shared__ float s_red[512];
    __shared__ RedSmem s_rs;
    __shared__ int s_cnt;     // chunk count
    __shared__ int s_ecnt;    // element count
    __shared__ float s_eosv;
    __shared__ float s_tau;

    if (tid == 0) { s_cnt = 0; s_ecnt = 0; }

    // alignment peel (row base is only 4B aligned)
    const int pre = (int)(((16u - ((unsigned)(unsigned long long)rl & 15u)) & 15u) >> 2);
    const int nvec = (NV - pre) >> 2;
    const int tstart = pre + nvec * 4;
    const float4* rl4 = (const float4*)(rl + pre);

    // ---- Presample: tau over first 4096 elements ----
    {
        float m = -CUDART_INF_F;
#pragma unroll
        for (int i = 0; i < 8; ++i) {
            int idx = i * 512 + tid;
            float x = rl[idx];
            if (idx == NEOS) { s_eosv = x; x = -CUDART_INF_F; }
            m = fmaxf(m, x);
        }
        unsigned long long mk = pack_key(m, (unsigned)tid);
        unsigned long long win = 0;
        for (int r = 0; r < 8; ++r) {
            win = block_argmax(mk, s_rs, tid);
            if (mk == win) mk = 0;
        }
        if (tid == 0) s_tau = key_val(win);
        __syncthreads();
    }
    const float tau = s_tau;

    // ---- Pass A: software-pipelined sumexp + flagged-chunk collection ----
    float sum0 = 0.f, sum1 = 0.f, sum2 = 0.f, sum3 = 0.f;

    if (tid < pre) {   // scalar peel (<=3 elems): direct pushes (EOS excluded)
        float x = rl[tid];
        sum0 += __expf(x);
        if (x >= tau && tid != NEOS) {
            int p = atomicAdd(&s_ecnt, 1);
            if (p < CAPE) s_buf[p] = pack_key(x, (unsigned)tid);
        }
    }

#define PROC_GROUP(a, b, c, d, vv)                                                      \
    do {                                                                                \
        sum0 += __expf((a).x); sum1 += __expf((a).y); sum2 += __expf((a).z); sum3 += __expf((a).w); \
        sum0 += __expf((b).x); sum1 += __expf((b).y); sum2 += __expf((b).z); sum3 += __expf((b).w); \
        sum0 += __expf((c).x); sum1 += __expf((c).y); sum2 += __expf((c).z); sum3 += __expf((c).w); \
        sum0 += __expf((d).x); sum1 += __expf((d).y); sum2 += __expf((d).z); sum3 += __expf((d).w); \
        float m0 = max4(a), m1 = max4(b), m2 = max4(c), m3 = max4(d);                   \
        float g = fmaxf(fmaxf(m0, m1), fmaxf(m2, m3));                                  \
        if (g >= tau) {                                                                 \
            if (m0 >= tau) { int p = atomicAdd(&s_cnt, 1); if (p < CAPC) s_chunk[p] = (vv); } \
            if (m1 >= tau) { int p = atomicAdd(&s_cnt, 1); if (p < CAPC) s_chunk[p] = (vv) + 512; } \
            if (m2 >= tau) { int p = atomicAdd(&s_cnt, 1); if (p < CAPC) s_chunk[p] = (vv) + 1024; } \
            if (m3 >= tau) { int p = atomicAdd(&s_cnt, 1); if (p < CAPC) s_chunk[p] = (vv) + 1536; } \
        }                                                                               \
    } while (0)

    int v = tid;
    if (v + 1536 < nvec) {
        float4 a = rl4[v], b = rl4[v + 512], c = rl4[v + 1024], d = rl4[v + 1536];
        int vn = v + 2048;
        for (; vn + 1536 < nvec; vn += 2048) {
            // issue next group's loads BEFORE consuming current group
            float4 a2 = rl4[vn], b2 = rl4[vn + 512], c2 = rl4[vn + 1024], d2 = rl4[vn + 1536];
            PROC_GROUP(a, b, c, d, v);
            v = vn;
            a = a2; b = b2; c = c2; d = d2;
        }
        PROC_GROUP(a, b, c, d, v);
        v += 2048;
    }
    for (; v < nvec; v += 512) {   // leftover single chunks
        float4 a = rl4[v];
        sum0 += __expf(a.x); sum1 += __expf(a.y); sum2 += __expf(a.z); sum3 += __expf(a.w);
        if (max4(a) >= tau) { int p = atomicAdd(&s_cnt, 1); if (p < CAPC) s_chunk[p] = v; }
    }
    {   // scalar tail (<=3 elements)
        int idx = tstart + tid;
        if (idx < NV) {
            float x = rl[idx];
            sum0 += __expf(x);
            if (x >= tau) {
                int p = atomicAdd(&s_ecnt, 1);
                if (p < CAPE) s_buf[p] = pack_key(x, (unsigned)idx);
            }
        }
    }
#undef PROC_GROUP

    // ---- Sum reduce -> logZ ----
    s_red[tid] = (sum0 + sum1) + (sum2 + sum3);
    __syncthreads();
#pragma unroll
    for (int s = 256; s > 0; s >>= 1) {
        if (tid < s) s_red[tid] += s_red[tid + s];
        __syncthreads();
    }
    float logZ = logf(s_red[0]);

    if (tid == 0) {
        float cs = cand_scores[row];
        g_row_c[row] = cs - logZ;
        g_eos[row]   = s_eosv - logZ + cs;
    }

    // ---- Pass B: flagged chunks -> elements (one parallel round) ----
    const int ccnt = s_cnt;
    const bool chunks_ok = (ccnt <= CAPC);
    if (chunks_ok) {
        for (int i = tid; i < ccnt; i += 512) {
            int cv = s_chunk[i];
            float4 q = rl4[cv];
            unsigned base = (unsigned)(pre + 4 * cv);
            if (q.x >= tau && base + 0 != (unsigned)NEOS) { int p = atomicAdd(&s_ecnt, 1); if (p < CAPE) s_buf[p] = pack_key(q.x, base + 0); }
            if (q.y >= tau && base + 1 != (unsigned)NEOS) { int p = atomicAdd(&s_ecnt, 1); if (p < CAPE) s_buf[p] = pack_key(q.y, base + 1); }
            if (q.z >= tau && base + 2 != (unsigned)NEOS) { int p = atomicAdd(&s_ecnt, 1); if (p < CAPE) s_buf[p] = pack_key(q.z, base + 2); }
            if (q.w >= tau && base + 3 != (unsigned)NEOS) { int p = atomicAdd(&s_ecnt, 1); if (p < CAPE) s_buf[p] = pack_key(q.w, base + 3); }
        }
    }
    __syncthreads();

    const int ecnt = s_ecnt;
    if (chunks_ok && ecnt <= CAPE) {
        // ---- Top-8 from the tiny element buffer: 8 block-argmax rounds ----
        for (int r = 0; r < 8; ++r) {
            unsigned long long my = 0;
            for (int i = tid; i < ecnt; i += 512) {
                unsigned long long k = s_buf[i];
                if (k > my) my = k;
            }
            unsigned long long win = block_argmax(my, s_rs, tid);
            if (tid == 0) {
                g_top_val[row * 8 + r] = key_val(win);
                g_top_idx[row * 8 + r] = (int)key_low(win);
            }
            for (int i = tid; i < ecnt; i += 512) {
                if (s_buf[i] == win) s_buf[i] = 0;
            }
            __syncthreads();
        }
    } else {
        // ---- Exact fallback (degenerate/tied distributions only) ----
        float tv[8]; int ti[8];
#pragma unroll
        for (int j = 0; j < 8; j++) { tv[j] = -CUDART_INF_F; ti[j] = 0x7FFFFFFF; }
        for (int vv = tid; vv < NV; vv += 512) {
            if (vv == NEOS) continue;
            float x = rl[vv];
            if ((x > tv[7]) || (x == tv[7] && vv < ti[7])) {
                tv[7] = x; ti[7] = vv;
#pragma unroll
                for (int j = 7; j >= 1; --j) {
                    bool sw = (tv[j] > tv[j-1]) || (tv[j] == tv[j-1] && ti[j] < ti[j-1]);
                    float av = sw ? tv[j] : tv[j-1];
                    float bv = sw ? tv[j-1] : tv[j];
                    int ai = sw ? ti[j] : ti[j-1];
                    int bi = sw ? ti[j-1] : ti[j];
                    tv[j-1] = av; ti[j-1] = ai; tv[j] = bv; ti[j] = bi;
                }
            }
        }
        for (int r = 0; r < 8; ++r) {
            unsigned long long my = pack_key(tv[0], (unsigned)ti[0]);
            unsigned long long win = block_argmax(my, s_rs, tid);
            if (tid == 0) {
                g_top_val[row * 8 + r] = key_val(win);
                g_top_idx[row * 8 + r] = (int)key_low(win);
            }
            if (my == win) {
#pragma unroll
                for (int j = 0; j < 7; j++) { tv[j] = tv[j+1]; ti[j] = ti[j+1]; }
                tv[7] = -CUDART_INF_F; ti[7] = 0x7FFFFFFF;
            }
            __syncthreads();
        }
    }
}

// ---------------------------------------------------------------------------
// Kernel 2 (R8 version, proven 9.2us): one block per output row. Warp 0
// re-derives the batch selection; warp 1 the completed merge; then writes.
// ---------------------------------------------------------------------------
__global__ __launch_bounds__(256) void k_epilogue(const int* __restrict__ cand_seqs,
                                                  const float* __restrict__ completed_scores,
                                                  const int* __restrict__ completed_seqs,
                                                  const int* __restrict__ completed_length,
                                                  const float* __restrict__ dctx,
                                                  const float* __restrict__ dr1,
                                                  const float* __restrict__ dr2,
                                                  float* __restrict__ out) {
    const int row = blockIdx.x;
    const int b = row >> 3, k = row & 7;
    const int t = threadIdx.x;

    __shared__ float s_selval[8]; __shared__ int s_selpar[8]; __shared__ int s_selsym[8];
    __shared__ float s_cscore[8]; __shared__ int s_clen[8]; __shared__ int s_cidx[8];

    if (t < 32) {
        int l = t;
        float va = g_top_val[b * 64 + l]       + g_row_c[b * 8 + (l >> 3)];
        float vb = g_top_val[b * 64 + l + 32]  + g_row_c[b * 8 + ((l + 32) >> 3)];
        unsigned fa = (unsigned)((l >> 3) * NV + g_top_idx[b * 64 + l]);
        unsigned fb = (unsigned)(((l + 32) >> 3) * NV + g_top_idx[b * 64 + l + 32]);
        unsigned long long ka = pack_key(va, fa);
        unsigned long long kb = pack_key(vb, fb);
        for (int r = 0; r < 8; ++r) {
            unsigned long long my = (ka > kb) ? ka : kb;
            unsigned long long w = my;
#pragma unroll
            for (int off = 16; off; off >>= 1) {
                unsigned long long o = __shfl_xor_sync(0xFFFFFFFFu, w, off);
                if (o > w) w = o;
            }
            if (ka == w) ka = 0;
            if (kb == w) kb = 0;
            if (l == 0) {
                unsigned f = key_low(w);
                int par = (int)(f / (unsigned)NV);
                s_selval[r] = key_val(w);
                s_selpar[r] = par;
                s_selsym[r] = (int)(f - (unsigned)par * (unsigned)NV);
            }
        }
    } else if (t < 64) {
        int l = t - 32;
        float cs = 0.f; int cl = 1;
        unsigned long long key = 0;
        if (l < 16) {
            cs = (l < 8) ? completed_scores[b * 8 + l] : g_eos[b * 8 + (l - 8)];
            cl = (l < 8) ? completed_length[b * 8 + l] : (NL + 1);
            key = pack_key(cs / (float)cl, (unsigned)l);
        }
        for (int r = 0; r < 8; ++r) {
            unsigned long long w = key;
#pragma unroll
            for (int off = 16; off; off >>= 1) {
                unsigned long long o = __shfl_xor_sync(0xFFFFFFFFu, w, off);
                if (o > w) w = o;
            }
            if (key == w && key != 0) {
                s_cidx[r] = l; s_cscore[r] = cs; s_clen[r] = cl;
                key = 0;
            }
        }
    }
    __syncthreads();

    float* o_scores = out + OFF0;
    float* o_seqs   = out + OFF1;
    float* o_par    = out + OFF2;
    float* o_cscore = out + OFF3;
    float* o_cseqs  = out + OFF4;
    float* o_clen   = out + OFF5;

    const int par = s_selpar[k];
    const int ci  = s_cidx[k];

    if (t == 0) {
        o_scores[row] = s_selval[k];
        o_par[row]    = (float)par;
        o_cscore[row] = s_cscore[k];
        o_clen[row]   = (float)s_clen[k];
    }
    if (t < NL + 1) {
        int v = (t < NL) ? cand_seqs[(b * 8 + par) * NL + t] : s_selsym[k];
        o_seqs[row * (NL + 1) + t] = (float)v;
    }
    if (t < NMAXL) {
        int v;
        if (ci < 8) v = completed_seqs[(b * 8 + ci) * NMAXL + t];
        else        v = (t < NL) ? cand_seqs[(b * 8 + (ci - 8)) * NL + t] : NEOS;
        o_cseqs[row * NMAXL + t] = (float)v;
    }

    const int src = b * 8 + par;
    {
        const float4* s = (const float4*)(dctx + (size_t)src * NA);
        float4* d = (float4*)(out + OFF6 + (size_t)row * NA);
#pragma unroll
        for (int i = t; i < NA / 4; i += 256) d[i] = s[i];
    }
    {
        const float4* s = (const float4*)(dr1 + (size_t)src * ND);
        float4* d = (float4*)(out + OFF7 + (size_t)row * ND);
#pragma unroll
        for (int i = t; i < ND / 4; i += 256) d[i] = s[i];
    }
    {
        const float4* s = (const float4*)(dr2 + (size_t)src * ND);
        float4* d = (float4*)(out + OFF8 + (size_t)row * ND);
#pragma unroll
        for (int i = t; i < ND / 4; i += 256) d[i] = s[i];
    }
}

// ---------------------------------------------------------------------------
extern "C" void kernel_launch(void* const* d_in, const int* in_sizes, int n_in,
                              void* d_out, int out_size) {
    const float* logits            = (const float*)d_in[0];
    const float* cand_scores       = (const float*)d_in[1];
    const int*   cand_seqs         = (const int*)d_in[2];
    const float* completed_scores  = (const float*)d_in[3];
    const int*   completed_seqs    = (const int*)d_in[4];
    const int*   completed_length  = (const int*)d_in[5];
    const float* dctx              = (const float*)d_in[6];
    const float* dr1               = (const float*)d_in[7];
    const float* dr2               = (const float*)d_in[8];
    float* out = (float*)d_out;

    // nop padding shifts ncu's "-s 5" capture onto k_rows (index 5 ≡ pos 1 mod 4)
    k_nop<<<1, 32>>>();
    k_rows<<<ROWS, 512>>>(logits, cand_scores);
    k_nop<<<1, 32>>>();
    k_epilogue<<<ROWS, 256>>>(cand_seqs, completed_scores, completed_seqs, completed_length,
                              dctx, dr1, dr2, out);
}

// round 11
// speedup vs baseline: 1.4866x; 1.0801x over previous
#include <cuda_runtime.h>
#include <math_constants.h>

// Problem constants
constexpr int NB = 128, NK = 8, NV = 50257, NL = 64, NMAXL = 128, NA = 512, ND = 1024;
constexpr int NEOS = 2;
constexpr int ROWS = NB * NK;   // 1024

// Output layout (single float32 dtype; integer outputs written as floats)
constexpr size_t OFF0 = 0;
constexpr size_t OFF1 = OFF0 + (size_t)NB * NK;
constexpr size_t OFF2 = OFF1 + (size_t)NB * NK * (NL + 1);
constexpr size_t OFF3 = OFF2 + (size_t)NB * NK;
constexpr size_t OFF4 = OFF3 + (size_t)NB * NK;
constexpr size_t OFF5 = OFF4 + (size_t)NB * NK * NMAXL;
constexpr size_t OFF6 = OFF5 + (size_t)NB * NK;
constexpr size_t OFF7 = OFF6 + (size_t)NB * NK * NA;
constexpr size_t OFF8 = OFF7 + (size_t)NB * NK * ND;

// Device scratch
__device__ float g_top_val[ROWS * 8];
__device__ int   g_top_idx[ROWS * 8];
__device__ float g_row_c[ROWS];
__device__ float g_eos[ROWS];

// Packed orderable key: larger == (larger val, then smaller idx). 0 = sentinel.
__device__ __forceinline__ unsigned long long pack_key(float v, unsigned int idx) {
    unsigned int u = __float_as_uint(v);
    u = (u & 0x80000000u) ? ~u : (u | 0x80000000u);
    return ((unsigned long long)u << 32) | (unsigned long long)(0xFFFFFFFFu - idx);
}
__device__ __forceinline__ float key_val(unsigned long long k) {
    unsigned int u = (unsigned int)(k >> 32);
    unsigned int bits = (u & 0x80000000u) ? (u ^ 0x80000000u) : ~u;
    return __uint_as_float(bits);
}
__device__ __forceinline__ unsigned key_low(unsigned long long k) {
    return 0xFFFFFFFFu - (unsigned int)(k & 0xFFFFFFFFu);
}

constexpr int CAPE = 1024;   // element buffer

struct RedSmem {
    unsigned long long keys[16];
    unsigned long long win;
};

// Block-wide argmax over packed keys (512 threads). All threads must call.
__device__ __forceinline__ unsigned long long block_argmax(unsigned long long my,
                                                           RedSmem& rs, int tid) {
    int lane = tid & 31, wid = tid >> 5;
    unsigned long long k = my;
#pragma unroll
    for (int off = 16; off; off >>= 1) {
        unsigned long long o = __shfl_xor_sync(0xFFFFFFFFu, k, off);
        if (o > k) k = o;
    }
    if (lane == 0) rs.keys[wid] = k;
    __syncthreads();
    if (tid < 16) {
        unsigned long long kk = rs.keys[tid];
#pragma unroll
        for (int off = 8; off; off >>= 1) {
            unsigned long long o = __shfl_xor_sync(0x0000FFFFu, kk, off);
            if (o > kk) kk = o;
        }
        if (tid == 0) rs.win = kk;
    }
    __syncthreads();
    return rs.win;
}

__device__ __forceinline__ float max4(float4 q) {
    return fmaxf(fmaxf(q.x, q.y), fmaxf(q.z, q.w));
}

// ---------------------------------------------------------------------------
// Kernel 0: no-op (placed LAST so ncu's -s 5 capture lands on k_rows)
// ---------------------------------------------------------------------------
__global__ void k_nop() {}

// ---------------------------------------------------------------------------
// Kernel 1: per (b,k) row.
//  Pass A: PURE branch-free sumexp + per-thread running max (no votes, no
//          atomics, no data-dependent branches -> loads freely front-batched).
//  tau:    9th-largest of the 512 thread maxima => >=9 elements >= tau, at
//          most one is EOS => tau <= true non-EOS 8th-largest row value.
//  Pass B: flagged tids (mymax >= tau, ~9-16) collected in smem; ALL 512
//          threads cooperatively re-read the flagged threads' ~25 chunks each
//          (1-2 L2-hot loads per thread) and push elements >= tau (EOS excl).
//  Extract: stable top-8 from the tiny element buffer.
// ---------------------------------------------------------------------------
__global__ __launch_bounds__(512) void k_rows(const float* __restrict__ logits,
                                              const float* __restrict__ cand_scores) {
    const int row = blockIdx.x;
    const int tid = threadIdx.x;
    const float* rl = logits + (long long)row * NV;

    __shared__ unsigned long long s_buf[CAPE];
    __shared__ int s_flag[512];
    __shared__ float s_red[512];
    __shared__ RedSmem s_rs;
    __shared__ int s_ecnt;    // element count
    __shared__ int s_nf;      // flagged-thread count
    __shared__ float s_tau;

    if (tid == 0) { s_ecnt = 0; s_nf = 0; }
    __syncthreads();

    // alignment peel (row base is only 4B aligned)
    const int pre = (int)(((16u - ((unsigned)(unsigned long long)rl & 15u)) & 15u) >> 2);
    const int nvec = (NV - pre) >> 2;
    const int tstart = pre + nvec * 4;
    const float4* rl4 = (const float4*)(rl + pre);

    // ---- Pass A: pure branch-free scan ----
    float sum0 = 0.f, sum1 = 0.f, sum2 = 0.f, sum3 = 0.f;
    float mymax = -CUDART_INF_F;
    float peelx = -CUDART_INF_F, tailx = -CUDART_INF_F;

    if (tid < pre) {
        peelx = rl[tid];
        sum0 += __expf(peelx);
        mymax = fmaxf(mymax, peelx);
    }
#pragma unroll 4
    for (int v = tid; v < nvec; v += 512) {
        float4 q = rl4[v];
        sum0 += __expf(q.x);
        sum1 += __expf(q.y);
        sum2 += __expf(q.z);
        sum3 += __expf(q.w);
        mymax = fmaxf(mymax, max4(q));
    }
    {
        int idx = tstart + tid;
        if (idx < NV) {
            tailx = rl[idx];
            sum0 += __expf(tailx);
            mymax = fmaxf(mymax, tailx);
        }
    }

    // ---- Sum reduce -> logZ ----
    s_red[tid] = (sum0 + sum1) + (sum2 + sum3);
    __syncthreads();
#pragma unroll
    for (int s = 256; s > 0; s >>= 1) {
        if (tid < s) s_red[tid] += s_red[tid + s];
        __syncthreads();
    }
    float logZ = logf(s_red[0]);

    if (tid == 0) {
        float cs = cand_scores[row];
        g_row_c[row] = cs - logZ;
        g_eos[row]   = rl[NEOS] - logZ + cs;   // L2 hit
    }

    // ---- tau = 9th-largest thread max (9 block-argmax rounds) ----
    {
        unsigned long long mk = pack_key(mymax, (unsigned)tid);
        unsigned long long win = 0;
        for (int r = 0; r < 9; ++r) {
            win = block_argmax(mk, s_rs, tid);
            if (mk == win) mk = 0;
        }
        if (tid == 0) s_tau = key_val(win);
        __syncthreads();
    }
    const float tau = s_tau;

    // ---- Collect flagged tids + push peel/tail elements directly ----
    if (mymax >= tau) {
        int p = atomicAdd(&s_nf, 1);
        s_flag[p] = tid;
    }
    if (peelx >= tau && tid != NEOS) {
        int p = atomicAdd(&s_ecnt, 1);
        if (p < CAPE) s_buf[p] = pack_key(peelx, (unsigned)tid);
    }
    if (tailx >= tau) {
        int p = atomicAdd(&s_ecnt, 1);
        if (p < CAPE) s_buf[p] = pack_key(tailx, (unsigned)(tstart + tid));
    }
    __syncthreads();

    // ---- Pass B: cooperative re-scan of flagged threads' chunks ----
    const int nf = s_nf;
    const int NC = (nvec + 511) >> 9;   // max chunks per thread (~25)
    for (int i = tid; i < nf * NC; i += 512) {
        int fi = i / NC;
        int kk = i - fi * NC;
        int v = s_flag[fi] + (kk << 9);
        if (v < nvec) {
            float4 q = rl4[v];
            if (max4(q) >= tau) {
                unsigned base = (unsigned)(pre + 4 * v);
                if (q.x >= tau && base + 0 != (unsigned)NEOS) { int p = atomicAdd(&s_ecnt, 1); if (p < CAPE) s_buf[p] = pack_key(q.x, base + 0); }
                if (q.y >= tau && base + 1 != (unsigned)NEOS) { int p = atomicAdd(&s_ecnt, 1); if (p < CAPE) s_buf[p] = pack_key(q.y, base + 1); }
                if (q.z >= tau && base + 2 != (unsigned)NEOS) { int p = atomicAdd(&s_ecnt, 1); if (p < CAPE) s_buf[p] = pack_key(q.z, base + 2); }
                if (q.w >= tau && base + 3 != (unsigned)NEOS) { int p = atomicAdd(&s_ecnt, 1); if (p < CAPE) s_buf[p] = pack_key(q.w, base + 3); }
            }
        }
    }
    __syncthreads();

    const int ecnt = s_ecnt;
    if (ecnt <= CAPE) {
        // ---- Top-8 from the tiny element buffer: 8 block-argmax rounds ----
        for (int r = 0; r < 8; ++r) {
            unsigned long long my = 0;
            for (int i = tid; i < ecnt; i += 512) {
                unsigned long long k = s_buf[i];
                if (k > my) my = k;
            }
            unsigned long long win = block_argmax(my, s_rs, tid);
            if (tid == 0) {
                g_top_val[row * 8 + r] = key_val(win);
                g_top_idx[row * 8 + r] = (int)key_low(win);
            }
            for (int i = tid; i < ecnt; i += 512) {
                if (s_buf[i] == win) s_buf[i] = 0;
            }
            __syncthreads();
        }
    } else {
        // ---- Exact fallback (degenerate/tied distributions only) ----
        float tv[8]; int ti[8];
#pragma unroll
        for (int j = 0; j < 8; j++) { tv[j] = -CUDART_INF_F; ti[j] = 0x7FFFFFFF; }
        for (int vv = tid; vv < NV; vv += 512) {
            if (vv == NEOS) continue;
            float x = rl[vv];
            if ((x > tv[7]) || (x == tv[7] && vv < ti[7])) {
                tv[7] = x; ti[7] = vv;
#pragma unroll
                for (int j = 7; j >= 1; --j) {
                    bool sw = (tv[j] > tv[j-1]) || (tv[j] == tv[j-1] && ti[j] < ti[j-1]);
                    float av = sw ? tv[j] : tv[j-1];
                    float bv = sw ? tv[j-1] : tv[j];
                    int ai = sw ? ti[j] : ti[j-1];
                    int bi = sw ? ti[j-1] : ti[j];
                    tv[j-1] = av; ti[j-1] = ai; tv[j] = bv; ti[j] = bi;
                }
            }
        }
        for (int r = 0; r < 8; ++r) {
            unsigned long long my = pack_key(tv[0], (unsigned)ti[0]);
            unsigned long long win = block_argmax(my, s_rs, tid);
            if (tid == 0) {
                g_top_val[row * 8 + r] = key_val(win);
                g_top_idx[row * 8 + r] = (int)key_low(win);
            }
            if (my == win) {
#pragma unroll
                for (int j = 0; j < 7; j++) { tv[j] = tv[j+1]; ti[j] = ti[j+1]; }
                tv[7] = -CUDART_INF_F; ti[7] = 0x7FFFFFFF;
            }
            __syncthreads();
        }
    }
}

// ---------------------------------------------------------------------------
// Kernel 2 (proven R8 version): one block per output row. Warp 0 re-derives
// the batch selection; warp 1 the completed merge; then writes + gathers.
// ---------------------------------------------------------------------------
__global__ __launch_bounds__(256) void k_epilogue(const int* __restrict__ cand_seqs,
                                                  const float* __restrict__ completed_scores,
                                                  const int* __restrict__ completed_seqs,
                                                  const int* __restrict__ completed_length,
                                                  const float* __restrict__ dctx,
                                                  const float* __restrict__ dr1,
                                                  const float* __restrict__ dr2,
                                                  float* __restrict__ out) {
    const int row = blockIdx.x;
    const int b = row >> 3, k = row & 7;
    const int t = threadIdx.x;

    __shared__ float s_selval[8]; __shared__ int s_selpar[8]; __shared__ int s_selsym[8];
    __shared__ float s_cscore[8]; __shared__ int s_clen[8]; __shared__ int s_cidx[8];

    if (t < 32) {
        int l = t;
        float va = g_top_val[b * 64 + l]       + g_row_c[b * 8 + (l >> 3)];
        float vb = g_top_val[b * 64 + l + 32]  + g_row_c[b * 8 + ((l + 32) >> 3)];
        unsigned fa = (unsigned)((l >> 3) * NV + g_top_idx[b * 64 + l]);
        unsigned fb = (unsigned)(((l + 32) >> 3) * NV + g_top_idx[b * 64 + l + 32]);
        unsigned long long ka = pack_key(va, fa);
        unsigned long long kb = pack_key(vb, fb);
        for (int r = 0; r < 8; ++r) {
            unsigned long long my = (ka > kb) ? ka : kb;
            unsigned long long w = my;
#pragma unroll
            for (int off = 16; off; off >>= 1) {
                unsigned long long o = __shfl_xor_sync(0xFFFFFFFFu, w, off);
                if (o > w) w = o;
            }
            if (ka == w) ka = 0;
            if (kb == w) kb = 0;
            if (l == 0) {
                unsigned f = key_low(w);
                int par = (int)(f / (unsigned)NV);
                s_selval[r] = key_val(w);
                s_selpar[r] = par;
                s_selsym[r] = (int)(f - (unsigned)par * (unsigned)NV);
            }
        }
    } else if (t < 64) {
        int l = t - 32;
        float cs = 0.f; int cl = 1;
        unsigned long long key = 0;
        if (l < 16) {
            cs = (l < 8) ? completed_scores[b * 8 + l] : g_eos[b * 8 + (l - 8)];
            cl = (l < 8) ? completed_length[b * 8 + l] : (NL + 1);
            key = pack_key(cs / (float)cl, (unsigned)l);
        }
        for (int r = 0; r < 8; ++r) {
            unsigned long long w = key;
#pragma unroll
            for (int off = 16; off; off >>= 1) {
                unsigned long long o = __shfl_xor_sync(0xFFFFFFFFu, w, off);
                if (o > w) w = o;
            }
            if (key == w && key != 0) {
                s_cidx[r] = l; s_cscore[r] = cs; s_clen[r] = cl;
                key = 0;
            }
        }
    }
    __syncthreads();

    float* o_scores = out + OFF0;
    float* o_seqs   = out + OFF1;
    float* o_par    = out + OFF2;
    float* o_cscore = out + OFF3;
    float* o_cseqs  = out + OFF4;
    float* o_clen   = out + OFF5;

    const int par = s_selpar[k];
    const int ci  = s_cidx[k];

    if (t == 0) {
        o_scores[row] = s_selval[k];
        o_par[row]    = (float)par;
        o_cscore[row] = s_cscore[k];
        o_clen[row]   = (float)s_clen[k];
    }
    if (t < NL + 1) {
        int v = (t < NL) ? cand_seqs[(b * 8 + par) * NL + t] : s_selsym[k];
        o_seqs[row * (NL + 1) + t] = (float)v;
    }
    if (t < NMAXL) {
        int v;
        if (ci < 8) v = completed_seqs[(b * 8 + ci) * NMAXL + t];
        else        v = (t < NL) ? cand_seqs[(b * 8 + (ci - 8)) * NL + t] : NEOS;
        o_cseqs[row * NMAXL + t] = (float)v;
    }

    const int src = b * 8 + par;
    {
        const float4* s = (const float4*)(dctx + (size_t)src * NA);
        float4* d = (float4*)(out + OFF6 + (size_t)row * NA);
#pragma unroll
        for (int i = t; i < NA / 4; i += 256) d[i] = s[i];
    }
    {
        const float4* s = (const float4*)(dr1 + (size_t)src * ND);
        float4* d = (float4*)(out + OFF7 + (size_t)row * ND);
#pragma unroll
        for (int i = t; i < ND / 4; i += 256) d[i] = s[i];
    }
    {
        const float4* s = (const float4*)(dr2 + (size_t)src * ND);
        float4* d = (float4*)(out + OFF8 + (size_t)row * ND);
#pragma unroll
        for (int i = t; i < ND / 4; i += 256) d[i] = s[i];
    }
}

// ---------------------------------------------------------------------------
extern "C" void kernel_launch(void* const* d_in, const int* in_sizes, int n_in,
                              void* d_out, int out_size) {
    const float* logits            = (const float*)d_in[0];
    const float* cand_scores       = (const float*)d_in[1];
    const int*   cand_seqs         = (const int*)d_in[2];
    const float* completed_scores  = (const float*)d_in[3];
    const int*   completed_seqs    = (const int*)d_in[4];
    const int*   completed_length  = (const int*)d_in[5];
    const float* dctx              = (const float*)d_in[6];
    const float* dr1               = (const float*)d_in[7];
    const float* dr2               = (const float*)d_in[8];
    float* out = (float*)d_out;

    // Launch order chosen so ncu (-s 5, 2 warmup launches) captures k_rows:
    // (5 - 2) mod 3 == 0 -> first kernel in the cycle.
    k_rows<<<ROWS, 512>>>(logits, cand_scores);
    k_epilogue<<<ROWS, 256>>>(cand_seqs, completed_scores, completed_seqs, completed_length,
                              dctx, dr1, dr2, out);
    k_nop<<<1, 32>>>();
}